// round 1
// baseline (speedup 1.0000x reference)
#include <cuda_runtime.h>
#include <cuda_bf16.h>

// Problem shape (fixed by reference): B=8, N=2048, D=128
#define B_ 8
#define N_ 2048
#define D_ 128

#define BM 64          // j-rows per block tile
#define BK 32          // k (i-dim) chunk for GEMM1
#define CP (2*D_ + 4)  // concat row pitch (floats), padded
#define WP (D_ + 4)    // W-transpose tile pitch (floats), padded

// scratch for degrees (no cudaMalloc allowed)
__device__ float g_degree[B_ * N_];

// ---------------------------------------------------------------------------
// Kernel 1: degree[b,j] = sum_i adj[b,j,i]   (one warp per row)
// ---------------------------------------------------------------------------
__global__ void degree_kernel(const float* __restrict__ adj) {
    int warp = (blockIdx.x * blockDim.x + threadIdx.x) >> 5;
    int lane = threadIdx.x & 31;
    if (warp >= B_ * N_) return;
    const float4* row = reinterpret_cast<const float4*>(adj + (size_t)warp * N_);
    float s = 0.f;
    #pragma unroll
    for (int t = 0; t < (N_ / 4) / 32; t++) {
        float4 v = row[t * 32 + lane];
        s += (v.x + v.y) + (v.z + v.w);
    }
    #pragma unroll
    for (int o = 16; o; o >>= 1) s += __shfl_xor_sync(0xffffffffu, s, o);
    if (lane == 0) g_degree[warp] = s;
}

// ---------------------------------------------------------------------------
// Kernel 2: fused  SN = cost^T @ E / deg ;  out = relu([E|SN] @ W^T + bias)
// Block: 256 threads, tile = 64 rows (j) x 128 cols (d). Thread = 8x4 microtile.
//   tc = tid & 31 (col group), tr = tid >> 5 (row group / warp id)
// ---------------------------------------------------------------------------
__global__ void __launch_bounds__(256, 2)
fused_kernel(const float* __restrict__ E,
             const float* __restrict__ cost,
             const float* __restrict__ W,
             const float* __restrict__ bias,
             float* __restrict__ out) {
    extern __shared__ float smem[];
    // stage-1 layout (front of smem)
    float* sCost = smem;              // [BK][BM]
    float* sE    = smem + BK * BM;    // [BK][D_]
    // stage-2 layout (reuses whole smem after sync)
    float* sConcat = smem;            // [BM][CP]
    float* sWt     = smem + BM * CP;  // [64][WP]  (k-major, transposed W chunk)

    const int b     = blockIdx.y;
    const int jBase = blockIdx.x * BM;
    const int tid   = threadIdx.x;
    const int tc    = tid & 31;
    const int tr    = tid >> 5;

    const float* Eb = E    + (size_t)b * N_ * D_;
    const float* Cb = cost + (size_t)b * N_ * N_;

    float acc[8][4];
    #pragma unroll
    for (int r = 0; r < 8; r++)
        #pragma unroll
        for (int c = 0; c < 4; c++) acc[r][c] = 0.f;

    // ---- Stage 1: SN-tile = cost^T @ E over K = N_ ----
    for (int k0 = 0; k0 < N_; k0 += BK) {
        // cost tile [BK][BM]: coalesced float4 along j
        #pragma unroll
        for (int it = 0; it < (BK * BM / 4) / 256; it++) {
            int f  = it * 256 + tid;          // 0..511
            int i  = f >> 4;                  // 0..31
            int j4 = f & 15;                  // 0..15
            float4 v = *reinterpret_cast<const float4*>(
                Cb + (size_t)(k0 + i) * N_ + jBase + j4 * 4);
            *reinterpret_cast<float4*>(sCost + i * BM + j4 * 4) = v;
        }
        // E tile [BK][D_]
        #pragma unroll
        for (int it = 0; it < (BK * D_ / 4) / 256; it++) {
            int f  = it * 256 + tid;          // 0..1023
            int i  = f >> 5;                  // 0..31
            int d4 = f & 31;                  // 0..31
            float4 v = *reinterpret_cast<const float4*>(
                Eb + (size_t)(k0 + i) * D_ + d4 * 4);
            *reinterpret_cast<float4*>(sE + i * D_ + d4 * 4) = v;
        }
        __syncthreads();
        #pragma unroll
        for (int kk = 0; kk < BK; kk++) {
            float4 bv = *reinterpret_cast<const float4*>(sE + kk * D_ + tc * 4);
            #pragma unroll
            for (int r = 0; r < 8; r++) {
                float a = sCost[kk * BM + tr * 8 + r];  // warp-broadcast
                acc[r][0] += a * bv.x;
                acc[r][1] += a * bv.y;
                acc[r][2] += a * bv.z;
                acc[r][3] += a * bv.w;
            }
        }
        __syncthreads();
    }

    // ---- Stage 2 prep: write SN/deg into concat smem, load E rows ----
    #pragma unroll
    for (int r = 0; r < 8; r++) {
        int row = tr * 8 + r;
        float rd = 1.0f / g_degree[b * N_ + jBase + row];
        float4 v = make_float4(acc[r][0] * rd, acc[r][1] * rd,
                               acc[r][2] * rd, acc[r][3] * rd);
        *reinterpret_cast<float4*>(sConcat + row * CP + D_ + tc * 4) = v;
    }
    #pragma unroll
    for (int it = 0; it < (BM * D_ / 4) / 256; it++) {
        int f   = it * 256 + tid;   // 0..2047
        int row = f >> 5;
        int d4  = f & 31;
        float4 v = *reinterpret_cast<const float4*>(
            Eb + (size_t)(jBase + row) * D_ + d4 * 4);
        *reinterpret_cast<float4*>(sConcat + row * CP + d4 * 4) = v;
    }

    float4 bv0 = *reinterpret_cast<const float4*>(bias + tc * 4);
    float acc2[8][4];
    #pragma unroll
    for (int r = 0; r < 8; r++) {
        acc2[r][0] = bv0.x; acc2[r][1] = bv0.y;
        acc2[r][2] = bv0.z; acc2[r][3] = bv0.w;
    }

    // ---- Stage 2: out-tile = concat @ W^T, K = 2D = 256 in chunks of 64 ----
    for (int kc = 0; kc < 2 * D_; kc += 64) {
        __syncthreads();  // concat writes visible / protect sWt reuse
        #pragma unroll
        for (int it = 0; it < (64 * D_) / 256; it++) {
            int f = it * 256 + tid;
            int d = f >> 6;          // 0..127
            int k = f & 63;          // 0..63, coalesced along k
            sWt[k * WP + d] = W[d * (2 * D_) + kc + k];
        }
        __syncthreads();
        #pragma unroll
        for (int k = 0; k < 64; k++) {
            float4 wv = *reinterpret_cast<const float4*>(sWt + k * WP + tc * 4);
            #pragma unroll
            for (int r = 0; r < 8; r++) {
                float c = sConcat[(tr * 8 + r) * CP + kc + k];  // broadcast
                acc2[r][0] += c * wv.x;
                acc2[r][1] += c * wv.y;
                acc2[r][2] += c * wv.z;
                acc2[r][3] += c * wv.w;
            }
        }
    }

    // ---- epilogue: relu + store ----
    float* Ob = out + (size_t)b * N_ * D_;
    #pragma unroll
    for (int r = 0; r < 8; r++) {
        int row = jBase + tr * 8 + r;
        float4 v;
        v.x = fmaxf(acc2[r][0], 0.f);
        v.y = fmaxf(acc2[r][1], 0.f);
        v.z = fmaxf(acc2[r][2], 0.f);
        v.w = fmaxf(acc2[r][3], 0.f);
        *reinterpret_cast<float4*>(Ob + (size_t)row * D_ + tc * 4) = v;
    }
}

// ---------------------------------------------------------------------------
extern "C" void kernel_launch(void* const* d_in, const int* in_sizes, int n_in,
                              void* d_out, int out_size) {
    const float* E    = (const float*)d_in[0];  // embeddings  (B,N,D)
    const float* adj  = (const float*)d_in[1];  // adjacency   (B,N,N)
    const float* cost = (const float*)d_in[2];  // cost        (B,N,N)
    const float* W    = (const float*)d_in[3];  // (D, 2D)
    const float* bias = (const float*)d_in[4];  // (D,)
    float* out = (float*)d_out;

    // degree: one warp per row, 8 rows per 256-thread block
    {
        int rows = B_ * N_;
        int blocks = (rows * 32 + 255) / 256;
        degree_kernel<<<blocks, 256>>>(adj);
    }

    // fused main kernel
    {
        size_t smem = (size_t)(BM * CP + 64 * WP) * sizeof(float);  // ~100 KB
        cudaFuncSetAttribute(fused_kernel,
                             cudaFuncAttributeMaxDynamicSharedMemorySize,
                             (int)smem);
        dim3 grid(N_ / BM, B_);
        fused_kernel<<<grid, 256, smem>>>(E, cost, W, bias, out);
    }
}

// round 2
// speedup vs baseline: 1.0242x; 1.0242x over previous
#include <cuda_runtime.h>
#include <cuda_bf16.h>

// Problem shape (fixed by reference): B=8, N=2048, D=128
#define B_ 8
#define N_ 2048
#define D_ 128

#define BM 64          // j-rows per block tile
#define BK 32          // k (i-dim) chunk for GEMM1
#define CP (2*D_ + 4)  // concat row pitch (floats), padded
#define WP (D_ + 4)    // W-transpose tile pitch (floats), padded

typedef unsigned long long u64;

// scratch for degrees (no cudaMalloc allowed)
__device__ float g_degree[B_ * N_];

// ---- packed f32x2 helpers (FFMA2 — 2 fp32 MACs per issue on sm_103a) ----
__device__ __forceinline__ u64 pk2(float x, float y) {
    u64 r; asm("mov.b64 %0,{%1,%2};" : "=l"(r) : "f"(x), "f"(y)); return r;
}
__device__ __forceinline__ float2 upk2(u64 v) {
    float2 f; asm("mov.b64 {%0,%1},%2;" : "=f"(f.x), "=f"(f.y) : "l"(v)); return f;
}
__device__ __forceinline__ u64 ffma2(u64 a, u64 b, u64 c) {
    u64 d; asm("fma.rn.f32x2 %0,%1,%2,%3;" : "=l"(d) : "l"(a), "l"(b), "l"(c)); return d;
}

// ---------------------------------------------------------------------------
// Kernel 1: degree[b,j] = sum_i adj[b,j,i]   (one warp per row)
// ---------------------------------------------------------------------------
__global__ void degree_kernel(const float* __restrict__ adj) {
    int warp = (blockIdx.x * blockDim.x + threadIdx.x) >> 5;
    int lane = threadIdx.x & 31;
    if (warp >= B_ * N_) return;
    const float4* row = reinterpret_cast<const float4*>(adj + (size_t)warp * N_);
    float s = 0.f;
    #pragma unroll
    for (int t = 0; t < (N_ / 4) / 32; t++) {
        float4 v = row[t * 32 + lane];
        s += (v.x + v.y) + (v.z + v.w);
    }
    #pragma unroll
    for (int o = 16; o; o >>= 1) s += __shfl_xor_sync(0xffffffffu, s, o);
    if (lane == 0) g_degree[warp] = s;
}

// ---------------------------------------------------------------------------
// Kernel 2: fused  SN = cost^T @ E / deg ;  out = relu([E|SN] @ W^T + bias)
// Block: 256 threads, tile = 64 rows (j) x 128 cols (d). Thread = 8x4 microtile
// computed as packed f32x2 pairs over the row dimension (stage 1) and the
// column dimension (stage 2).
// ---------------------------------------------------------------------------
__global__ void __launch_bounds__(256, 2)
fused_kernel(const float* __restrict__ E,
             const float* __restrict__ cost,
             const float* __restrict__ W,
             const float* __restrict__ bias,
             float* __restrict__ out) {
    extern __shared__ float smem[];
    // stage-1 layout (front of smem)
    float* sCost = smem;              // [BK][BM]
    float* sE    = smem + BK * BM;    // [BK][D_]
    // stage-2 layout (reuses whole smem after sync)
    float* sConcat = smem;            // [BM][CP]
    float* sWt     = smem + BM * CP;  // [64][WP]  (k-major, transposed W chunk)

    const int b     = blockIdx.y;
    const int jBase = blockIdx.x * BM;
    const int tid   = threadIdx.x;
    const int tc    = tid & 31;
    const int tr    = tid >> 5;

    const float* Eb = E    + (size_t)b * N_ * D_;
    const float* Cb = cost + (size_t)b * N_ * N_;

    // accp[c][rp]: packed pair of rows (2rp, 2rp+1) for output column c
    u64 accp[4][4];
    {
        u64 z = pk2(0.f, 0.f);
        #pragma unroll
        for (int c = 0; c < 4; c++)
            #pragma unroll
            for (int rp = 0; rp < 4; rp++) accp[c][rp] = z;
    }

    // ---- Stage 1: SN-tile = cost^T @ E over K = N_ ----
    for (int k0 = 0; k0 < N_; k0 += BK) {
        // cost tile [BK][BM]: coalesced float4 along j
        #pragma unroll
        for (int it = 0; it < (BK * BM / 4) / 256; it++) {
            int f  = it * 256 + tid;          // 0..511
            int i  = f >> 4;                  // 0..31
            int j4 = f & 15;                  // 0..15
            float4 v = *reinterpret_cast<const float4*>(
                Cb + (size_t)(k0 + i) * N_ + jBase + j4 * 4);
            *reinterpret_cast<float4*>(sCost + i * BM + j4 * 4) = v;
        }
        // E tile [BK][D_]
        #pragma unroll
        for (int it = 0; it < (BK * D_ / 4) / 256; it++) {
            int f  = it * 256 + tid;          // 0..1023
            int i  = f >> 5;                  // 0..31
            int d4 = f & 31;                  // 0..31
            float4 v = *reinterpret_cast<const float4*>(
                Eb + (size_t)(k0 + i) * D_ + d4 * 4);
            *reinterpret_cast<float4*>(sE + i * D_ + d4 * 4) = v;
        }
        __syncthreads();
        #pragma unroll
        for (int kk = 0; kk < BK; kk++) {
            float4 bv = *reinterpret_cast<const float4*>(sE + kk * D_ + tc * 4);
            u64 bx = pk2(bv.x, bv.x);
            u64 by = pk2(bv.y, bv.y);
            u64 bz = pk2(bv.z, bv.z);
            u64 bw = pk2(bv.w, bv.w);
            // row pairs come packed straight out of shared (uniform -> broadcast)
            const u64* ap = reinterpret_cast<const u64*>(sCost + kk * BM + tr * 8);
            #pragma unroll
            for (int rp = 0; rp < 4; rp++) {
                u64 a = ap[rp];
                accp[0][rp] = ffma2(a, bx, accp[0][rp]);
                accp[1][rp] = ffma2(a, by, accp[1][rp]);
                accp[2][rp] = ffma2(a, bz, accp[2][rp]);
                accp[3][rp] = ffma2(a, bw, accp[3][rp]);
            }
        }
        __syncthreads();
    }

    // ---- Stage 2 prep: write SN/deg into concat smem, load E rows ----
    #pragma unroll
    for (int rp = 0; rp < 4; rp++) {
        int row0 = tr * 8 + 2 * rp;
        float rd0 = 1.0f / g_degree[b * N_ + jBase + row0];
        float rd1 = 1.0f / g_degree[b * N_ + jBase + row0 + 1];
        float2 a0 = upk2(accp[0][rp]);
        float2 a1 = upk2(accp[1][rp]);
        float2 a2 = upk2(accp[2][rp]);
        float2 a3 = upk2(accp[3][rp]);
        *reinterpret_cast<float4*>(sConcat + row0 * CP + D_ + tc * 4) =
            make_float4(a0.x * rd0, a1.x * rd0, a2.x * rd0, a3.x * rd0);
        *reinterpret_cast<float4*>(sConcat + (row0 + 1) * CP + D_ + tc * 4) =
            make_float4(a0.y * rd1, a1.y * rd1, a2.y * rd1, a3.y * rd1);
    }
    #pragma unroll
    for (int it = 0; it < (BM * D_ / 4) / 256; it++) {
        int f   = it * 256 + tid;   // 0..2047
        int row = f >> 5;
        int d4  = f & 31;
        float4 v = *reinterpret_cast<const float4*>(
            Eb + (size_t)(jBase + row) * D_ + d4 * 4);
        *reinterpret_cast<float4*>(sConcat + row * CP + d4 * 4) = v;
    }

    // acc2[r][cp]: packed column pairs (c0,c1) and (c2,c3), init with bias
    u64 acc2[8][2];
    {
        u64 b01 = *reinterpret_cast<const u64*>(bias + tc * 4);
        u64 b23 = *reinterpret_cast<const u64*>(bias + tc * 4 + 2);
        #pragma unroll
        for (int r = 0; r < 8; r++) { acc2[r][0] = b01; acc2[r][1] = b23; }
    }

    // ---- Stage 2: out-tile = concat @ W^T, K = 2D = 256 in chunks of 64 ----
    for (int kc = 0; kc < 2 * D_; kc += 64) {
        __syncthreads();  // concat writes visible / protect sWt reuse
        #pragma unroll
        for (int it = 0; it < (64 * D_) / 256; it++) {
            int f = it * 256 + tid;
            int d = f >> 6;          // 0..127
            int k = f & 63;          // 0..63, coalesced along k
            sWt[k * WP + d] = W[d * (2 * D_) + kc + k];
        }
        __syncthreads();
        #pragma unroll
        for (int k = 0; k < 64; k++) {
            u64 w01 = *reinterpret_cast<const u64*>(sWt + k * WP + tc * 4);
            u64 w23 = *reinterpret_cast<const u64*>(sWt + k * WP + tc * 4 + 2);
            #pragma unroll
            for (int r = 0; r < 8; r++) {
                float cv = sConcat[(tr * 8 + r) * CP + kc + k];  // broadcast
                u64 cd = pk2(cv, cv);
                acc2[r][0] = ffma2(cd, w01, acc2[r][0]);
                acc2[r][1] = ffma2(cd, w23, acc2[r][1]);
            }
        }
    }

    // ---- epilogue: relu + store ----
    float* Ob = out + (size_t)b * N_ * D_;
    #pragma unroll
    for (int r = 0; r < 8; r++) {
        int row = jBase + tr * 8 + r;
        float2 v01 = upk2(acc2[r][0]);
        float2 v23 = upk2(acc2[r][1]);
        float4 v;
        v.x = fmaxf(v01.x, 0.f);
        v.y = fmaxf(v01.y, 0.f);
        v.z = fmaxf(v23.x, 0.f);
        v.w = fmaxf(v23.y, 0.f);
        *reinterpret_cast<float4*>(Ob + (size_t)row * D_ + tc * 4) = v;
    }
}

// ---------------------------------------------------------------------------
extern "C" void kernel_launch(void* const* d_in, const int* in_sizes, int n_in,
                              void* d_out, int out_size) {
    const float* E    = (const float*)d_in[0];  // embeddings  (B,N,D)
    const float* adj  = (const float*)d_in[1];  // adjacency   (B,N,N)
    const float* cost = (const float*)d_in[2];  // cost        (B,N,N)
    const float* W    = (const float*)d_in[3];  // (D, 2D)
    const float* bias = (const float*)d_in[4];  // (D,)
    float* out = (float*)d_out;

    // degree: one warp per row, 8 rows per 256-thread block
    {
        int rows = B_ * N_;
        int blocks = (rows * 32 + 255) / 256;
        degree_kernel<<<blocks, 256>>>(adj);
    }

    // fused main kernel
    {
        size_t smem = (size_t)(BM * CP + 64 * WP) * sizeof(float);  // ~100 KB
        cudaFuncSetAttribute(fused_kernel,
                             cudaFuncAttributeMaxDynamicSharedMemorySize,
                             (int)smem);
        dim3 grid(N_ / BM, B_);
        fused_kernel<<<grid, 256, smem>>>(E, cost, W, bias, out);
    }
}